// round 4
// baseline (speedup 1.0000x reference)
#include <cuda_runtime.h>
#include <cuda_bf16.h>
#include <cstdint>
#include <math.h>

#define N_NODES 20000
#define N_EDGES 160000
#define D 512
#define N_GRAPHS 16
#define NODES_PER_GRAPH 1250
#define N_LAYERS 4

// ---------------------------------------------------------------------------
// Device scratch (static globals — no allocations allowed)
// ---------------------------------------------------------------------------
__device__ float g_h[N_NODES * D];                 // activations (scaled for l<3, raw for l==3)
__device__ __nv_bfloat16 g_a0[N_NODES * D];        // aggregated input, bf16 hi
__device__ __nv_bfloat16 g_a1[N_NODES * D];        // aggregated input, bf16 lo
__device__ __nv_bfloat16 g_wt0[N_LAYERS * D * D];  // W^T bf16 hi, [layer][n][k]
__device__ __nv_bfloat16 g_wt1[N_LAYERS * D * D];  // W^T bf16 lo
__device__ float g_onorm[N_NODES];
__device__ float g_inorm[N_NODES];
__device__ int g_outdeg[N_NODES];
__device__ int g_indeg[N_NODES];
__device__ int g_rowoff[N_NODES + 1];
__device__ int g_cursor[N_NODES];
__device__ int g_csr[N_EDGES];                     // src ids grouped by dst

__device__ __forceinline__ uint32_t smem_u32(const void* p) {
    uint32_t a;
    asm("{ .reg .u64 t; cvta.to.shared.u64 t, %1; cvt.u32.u64 %0, t; }" : "=r"(a) : "l"(p));
    return a;
}

__device__ __forceinline__ void cp_async_16(uint32_t dst, const void* src, int src_size) {
    asm volatile("cp.async.cg.shared.global [%0], [%1], 16, %2;"
                 :: "r"(dst), "l"(src), "r"(src_size) : "memory");
}

__device__ __forceinline__ void ldsm_x4(uint32_t* r, uint32_t addr) {
    asm volatile("ldmatrix.sync.aligned.m8n8.x4.shared.b16 {%0,%1,%2,%3}, [%4];"
                 : "=r"(r[0]), "=r"(r[1]), "=r"(r[2]), "=r"(r[3]) : "r"(addr));
}

__device__ __forceinline__ void mma_16816(float* d, const uint32_t* a,
                                          uint32_t b0, uint32_t b1) {
    asm volatile(
        "mma.sync.aligned.m16n8k16.row.col.f32.bf16.bf16.f32 "
        "{%0,%1,%2,%3}, {%4,%5,%6,%7}, {%8,%9}, {%0,%1,%2,%3};"
        : "+f"(d[0]), "+f"(d[1]), "+f"(d[2]), "+f"(d[3])
        : "r"(a[0]), "r"(a[1]), "r"(a[2]), "r"(a[3]), "r"(b0), "r"(b1));
}

// ---------------------------------------------------------------------------
// Graph preprocessing
// ---------------------------------------------------------------------------
__global__ void zero_deg_kernel() {
    int i = blockIdx.x * blockDim.x + threadIdx.x;
    if (i < N_NODES) { g_outdeg[i] = 0; g_indeg[i] = 0; }
}

__global__ void degree_kernel(const int* __restrict__ src, const int* __restrict__ dst) {
    int e = blockIdx.x * blockDim.x + threadIdx.x;
    if (e < N_EDGES) {
        atomicAdd(&g_outdeg[src[e]], 1);
        atomicAdd(&g_indeg[dst[e]], 1);
    }
}

__global__ void norm_kernel() {
    int i = blockIdx.x * blockDim.x + threadIdx.x;
    if (i < N_NODES) {
        int od = g_outdeg[i];
        int id = g_indeg[i];
        g_onorm[i] = od > 0 ? 1.0f / sqrtf((float)od) : 0.0f;
        g_inorm[i] = id > 0 ? 1.0f / sqrtf((float)id) : 0.0f;
    }
}

// Single-block shuffle-based exclusive scan of g_indeg -> g_rowoff / g_cursor
__global__ void scan_kernel() {
    const int CH = (N_NODES + 1023) / 1024;  // 20
    __shared__ int wsum[32];
    int tid = threadIdx.x;
    int base = tid * CH;
    int local[CH];
    int s = 0;
#pragma unroll
    for (int i = 0; i < CH; i++) {
        int idx = base + i;
        int v = (idx < N_NODES) ? g_indeg[idx] : 0;
        local[i] = s;
        s += v;
    }
    int lane = tid & 31, w = tid >> 5;
    int incl = s;
#pragma unroll
    for (int off = 1; off < 32; off <<= 1) {
        int n = __shfl_up_sync(0xffffffffu, incl, off);
        if (lane >= off) incl += n;
    }
    if (lane == 31) wsum[w] = incl;
    __syncthreads();
    if (w == 0) {
        int x = wsum[lane];
#pragma unroll
        for (int off = 1; off < 32; off <<= 1) {
            int n = __shfl_up_sync(0xffffffffu, x, off);
            if (lane >= off) x += n;
        }
        wsum[lane] = x;
    }
    __syncthreads();
    int excl = incl - s + (w > 0 ? wsum[w - 1] : 0);
#pragma unroll
    for (int i = 0; i < CH; i++) {
        int idx = base + i;
        if (idx < N_NODES) {
            int v = excl + local[i];
            g_rowoff[idx] = v;
            g_cursor[idx] = v;
        }
    }
    if (tid == 1023) g_rowoff[N_NODES] = wsum[31];
}

__global__ void fill_kernel(const int* __restrict__ src, const int* __restrict__ dst) {
    int e = blockIdx.x * blockDim.x + threadIdx.x;
    if (e < N_EDGES) {
        int d = dst[e];
        int pos = atomicAdd(&g_cursor[d], 1);
        g_csr[pos] = src[e];
    }
}

// ---------------------------------------------------------------------------
// W transpose + bf16 split for all layers: WT[layer][n][k] = W[k][n], hi/lo
// ---------------------------------------------------------------------------
__global__ void wsplit_kernel(const float* __restrict__ W0, const float* __restrict__ W1,
                              const float* __restrict__ W2, const float* __restrict__ W3) {
    __shared__ float tile[32][33];
    int layer = blockIdx.z;
    const float* W = layer == 0 ? W0 : layer == 1 ? W1 : layer == 2 ? W2 : W3;
    int k0 = blockIdx.x * 32, n0 = blockIdx.y * 32;
    for (int i = threadIdx.y; i < 32; i += 8)
        tile[i][threadIdx.x] = W[(size_t)(k0 + i) * D + n0 + threadIdx.x];
    __syncthreads();
    for (int i = threadIdx.y; i < 32; i += 8) {
        float x = tile[threadIdx.x][i];                       // W[k0+tx][n0+i]
        __nv_bfloat16 hi = __float2bfloat16(x);
        float r = x - __bfloat162float(hi);
        size_t idx = (size_t)layer * D * D + (size_t)(n0 + i) * D + (k0 + threadIdx.x);
        g_wt0[idx] = hi;
        g_wt1[idx] = __float2bfloat16(r);
    }
}

// ---------------------------------------------------------------------------
// CSR aggregation (4-edge unrolled) fused with in_norm scale + bf16 split.
// WEIGHTED=1: input rows are unscaled (layer 0 / feat) -> multiply out_norm per edge.
// WEIGHTED=0: input rows already carry out_norm (written by GEMM epilogue).
// ---------------------------------------------------------------------------
template <int WEIGHTED>
__global__ __launch_bounds__(128)
void agg_kernel(const float* __restrict__ h) {
    int node = blockIdx.x;
    int lane4 = threadIdx.x * 4;
    int beg = g_rowoff[node], end = g_rowoff[node + 1];
    float ax = 0.f, ay = 0.f, az = 0.f, aw = 0.f;

    int e = beg;
    for (; e + 4 <= end; e += 4) {
        int s0 = g_csr[e], s1 = g_csr[e + 1], s2 = g_csr[e + 2], s3 = g_csr[e + 3];
        float4 v0 = *reinterpret_cast<const float4*>(&h[(size_t)s0 * D + lane4]);
        float4 v1 = *reinterpret_cast<const float4*>(&h[(size_t)s1 * D + lane4]);
        float4 v2 = *reinterpret_cast<const float4*>(&h[(size_t)s2 * D + lane4]);
        float4 v3 = *reinterpret_cast<const float4*>(&h[(size_t)s3 * D + lane4]);
        if (WEIGHTED) {
            float w0 = g_onorm[s0], w1 = g_onorm[s1], w2 = g_onorm[s2], w3 = g_onorm[s3];
            ax = fmaf(v0.x, w0, ax); ay = fmaf(v0.y, w0, ay); az = fmaf(v0.z, w0, az); aw = fmaf(v0.w, w0, aw);
            ax = fmaf(v1.x, w1, ax); ay = fmaf(v1.y, w1, ay); az = fmaf(v1.z, w1, az); aw = fmaf(v1.w, w1, aw);
            ax = fmaf(v2.x, w2, ax); ay = fmaf(v2.y, w2, ay); az = fmaf(v2.z, w2, az); aw = fmaf(v2.w, w2, aw);
            ax = fmaf(v3.x, w3, ax); ay = fmaf(v3.y, w3, ay); az = fmaf(v3.z, w3, az); aw = fmaf(v3.w, w3, aw);
        } else {
            ax += v0.x + v1.x + v2.x + v3.x;
            ay += v0.y + v1.y + v2.y + v3.y;
            az += v0.z + v1.z + v2.z + v3.z;
            aw += v0.w + v1.w + v2.w + v3.w;
        }
    }
    for (; e < end; ++e) {
        int s = g_csr[e];
        float4 v = *reinterpret_cast<const float4*>(&h[(size_t)s * D + lane4]);
        float w = WEIGHTED ? g_onorm[s] : 1.0f;
        ax = fmaf(v.x, w, ax); ay = fmaf(v.y, w, ay);
        az = fmaf(v.z, w, az); aw = fmaf(v.w, w, aw);
    }

    float sc = g_inorm[node];
    ax *= sc; ay *= sc; az *= sc; aw *= sc;

    __nv_bfloat162 h01 = __floats2bfloat162_rn(ax, ay);
    __nv_bfloat162 h23 = __floats2bfloat162_rn(az, aw);
    float rx = ax - __bfloat162float(__low2bfloat16(h01));
    float ry = ay - __bfloat162float(__high2bfloat16(h01));
    float rz = az - __bfloat162float(__low2bfloat16(h23));
    float rw = aw - __bfloat162float(__high2bfloat16(h23));
    __nv_bfloat162 l01 = __floats2bfloat162_rn(rx, ry);
    __nv_bfloat162 l23 = __floats2bfloat162_rn(rz, rw);

    size_t off = (size_t)node * D + lane4;
    uint2 hiword, loword;
    hiword.x = *reinterpret_cast<uint32_t*>(&h01);
    hiword.y = *reinterpret_cast<uint32_t*>(&h23);
    loword.x = *reinterpret_cast<uint32_t*>(&l01);
    loword.y = *reinterpret_cast<uint32_t*>(&l23);
    *reinterpret_cast<uint2*>(&g_a0[off]) = hiword;
    *reinterpret_cast<uint2*>(&g_a1[off]) = loword;
}

// ---------------------------------------------------------------------------
// HMMA GEMM: C = (A0+A1)@(B0+B1)^T + bias, bf16x3 (A0B0+A0B1+A1B0).
// CTA 128x128, BK=32, 256 threads, 3-stage cp.async pipeline, 1 sync/chunk.
// mode==1: C = out_norm[row] * relu(acc+bias)   (layers 0-2)
// mode==0: C = acc + bias                       (layer 3)
// ---------------------------------------------------------------------------
#define BM 128
#define BN 128
#define BK 32
#define NCHUNK (D / BK)            // 16
#define NSTAGE 3
#define PAD_K 40                   // elements per smem row (80 bytes)
#define TILE_BYTES (128 * PAD_K * 2)     // 10240
#define STAGE_BYTES (4 * TILE_BYTES)     // 40960 (A0,A1,B0,B1)
#define GEMM_SMEM (NSTAGE * STAGE_BYTES) // 122880

__device__ __forceinline__ void gemm_load_stage(
    uint32_t sb, int c, int m0, int n0, int tid,
    const __nv_bfloat16* wt0, const __nv_bfloat16* wt1)
{
    int k0 = c * BK;
    uint32_t stb = sb + (uint32_t)(c % NSTAGE) * STAGE_BYTES;
#pragma unroll
    for (int i = 0; i < 8; i++) {
        int id = tid + i * 256;
        int t = id >> 9;                 // tile: 0=A0 1=A1 2=B0 3=B1
        int r = (id >> 2) & 127;         // row within tile
        int kc = id & 3;                 // 16B chunk within BK
        uint32_t dst = stb + (uint32_t)t * TILE_BYTES + (uint32_t)r * (PAD_K * 2) + kc * 16;
        const __nv_bfloat16* g;
        int size = 16;
        if (t < 2) {
            int row = m0 + r;
            const __nv_bfloat16* base = (t == 0) ? g_a0 : g_a1;
            if (row >= N_NODES) { row = 0; size = 0; }
            g = base + (size_t)row * D + k0 + kc * 8;
        } else {
            const __nv_bfloat16* base = (t == 2) ? wt0 : wt1;
            g = base + (size_t)(n0 + r) * D + k0 + kc * 8;
        }
        cp_async_16(dst, g, size);
    }
    asm volatile("cp.async.commit_group;" ::: "memory");
}

__global__ __launch_bounds__(256)
void hgemm_kernel(const float* __restrict__ bias, float* __restrict__ C,
                  int layer, int mode)
{
    extern __shared__ char smem[];
    uint32_t sb = smem_u32(smem);
    int tid = threadIdx.x;
    int lane = tid & 31, wid = tid >> 5;
    int m0 = blockIdx.y * BM;
    int n0 = blockIdx.x * BN;
    int wm = (wid & 3) * 32;
    int wn = (wid >> 2) * 64;

    const __nv_bfloat16* wt0 = g_wt0 + (size_t)layer * D * D;
    const __nv_bfloat16* wt1 = g_wt1 + (size_t)layer * D * D;

    float acc[2][8][4];
#pragma unroll
    for (int i = 0; i < 2; i++)
#pragma unroll
        for (int j = 0; j < 8; j++)
#pragma unroll
            for (int k = 0; k < 4; k++) acc[i][j][k] = 0.0f;

    int lrow = lane & 15;
    uint32_t lcolb = (uint32_t)(lane >> 4) * 16;

    gemm_load_stage(sb, 0, m0, n0, tid, wt0, wt1);
    gemm_load_stage(sb, 1, m0, n0, tid, wt0, wt1);

#pragma unroll 1
    for (int c = 0; c < NCHUNK; ++c) {
        asm volatile("cp.async.wait_group 1;" ::: "memory");
        __syncthreads();
        if (c + 2 < NCHUNK)
            gemm_load_stage(sb, c + 2, m0, n0, tid, wt0, wt1);

        uint32_t stb = sb + (uint32_t)(c % NSTAGE) * STAGE_BYTES;
        uint32_t a0t = stb;
        uint32_t a1t = stb + TILE_BYTES;
        uint32_t b0t = stb + 2 * TILE_BYTES;
        uint32_t b1t = stb + 3 * TILE_BYTES;

#pragma unroll
        for (int kk = 0; kk < BK; kk += 16) {
            uint32_t kb = (uint32_t)kk * 2 + lcolb;
            uint32_t af[2][4], ag[2][4], bf[4][4];
#pragma unroll
            for (int mi = 0; mi < 2; mi++)
                ldsm_x4(af[mi], a0t + (uint32_t)(wm + mi * 16 + lrow) * (PAD_K * 2) + kb);
#pragma unroll
            for (int nb = 0; nb < 4; nb++)
                ldsm_x4(bf[nb], b0t + (uint32_t)(wn + nb * 16 + lrow) * (PAD_K * 2) + kb);
#pragma unroll
            for (int mi = 0; mi < 2; mi++)
#pragma unroll
                for (int nb = 0; nb < 4; nb++) {
                    mma_16816(acc[mi][nb * 2 + 0], af[mi], bf[nb][0], bf[nb][2]);
                    mma_16816(acc[mi][nb * 2 + 1], af[mi], bf[nb][1], bf[nb][3]);
                }
#pragma unroll
            for (int mi = 0; mi < 2; mi++)
                ldsm_x4(ag[mi], a1t + (uint32_t)(wm + mi * 16 + lrow) * (PAD_K * 2) + kb);
#pragma unroll
            for (int mi = 0; mi < 2; mi++)
#pragma unroll
                for (int nb = 0; nb < 4; nb++) {
                    mma_16816(acc[mi][nb * 2 + 0], ag[mi], bf[nb][0], bf[nb][2]);
                    mma_16816(acc[mi][nb * 2 + 1], ag[mi], bf[nb][1], bf[nb][3]);
                }
#pragma unroll
            for (int nb = 0; nb < 4; nb++)
                ldsm_x4(bf[nb], b1t + (uint32_t)(wn + nb * 16 + lrow) * (PAD_K * 2) + kb);
#pragma unroll
            for (int mi = 0; mi < 2; mi++)
#pragma unroll
                for (int nb = 0; nb < 4; nb++) {
                    mma_16816(acc[mi][nb * 2 + 0], af[mi], bf[nb][0], bf[nb][2]);
                    mma_16816(acc[mi][nb * 2 + 1], af[mi], bf[nb][1], bf[nb][3]);
                }
        }
        __syncthreads();
    }

    // Epilogue
    int rbase = m0 + wm + (lane >> 2);
    int cbase = n0 + wn + (lane & 3) * 2;
#pragma unroll
    for (int mi = 0; mi < 2; mi++) {
        int r0 = rbase + mi * 16;
        int r1 = r0 + 8;
        bool v0 = r0 < N_NODES, v1 = r1 < N_NODES;
        float s0 = (mode && v0) ? g_onorm[r0] : 1.0f;
        float s1 = (mode && v1) ? g_onorm[r1] : 1.0f;
#pragma unroll
        for (int ni = 0; ni < 8; ni++) {
            int col = cbase + ni * 8;
            float2 bv = *reinterpret_cast<const float2*>(&bias[col]);
            float2 o0, o1;
            o0.x = acc[mi][ni][0] + bv.x; o0.y = acc[mi][ni][1] + bv.y;
            o1.x = acc[mi][ni][2] + bv.x; o1.y = acc[mi][ni][3] + bv.y;
            if (mode) {
                o0.x = fmaxf(o0.x, 0.f) * s0; o0.y = fmaxf(o0.y, 0.f) * s0;
                o1.x = fmaxf(o1.x, 0.f) * s1; o1.y = fmaxf(o1.y, 0.f) * s1;
            }
            if (v0) *reinterpret_cast<float2*>(&C[(size_t)r0 * D + col]) = o0;
            if (v1) *reinterpret_cast<float2*>(&C[(size_t)r1 * D + col]) = o1;
        }
    }
}

// ---------------------------------------------------------------------------
// Mean pool per graph (graphs are contiguous blocks of 1250 nodes)
// ---------------------------------------------------------------------------
__global__ void pool_kernel(float* __restrict__ out) {
    int g = blockIdx.x;
    int c = blockIdx.y * 128 + threadIdx.x;
    const float* base = g_h + (size_t)g * NODES_PER_GRAPH * D;
    float s0 = 0.f, s1 = 0.f;
#pragma unroll 4
    for (int i = 0; i < NODES_PER_GRAPH; i += 2) {
        s0 += base[(size_t)i * D + c];
        s1 += base[(size_t)(i + 1) * D + c];
    }
    out[g * D + c] = (s0 + s1) * (1.0f / (float)NODES_PER_GRAPH);
}

// ---------------------------------------------------------------------------
// Launch
// ---------------------------------------------------------------------------
extern "C" void kernel_launch(void* const* d_in, const int* in_sizes, int n_in,
                              void* d_out, int out_size) {
    const float* feat = (const float*)d_in[0];
    const int* src = (const int*)d_in[1];
    const int* dst = (const int*)d_in[2];
    const float* W[4] = {(const float*)d_in[4], (const float*)d_in[6],
                         (const float*)d_in[8], (const float*)d_in[10]};
    const float* B[4] = {(const float*)d_in[5], (const float*)d_in[7],
                         (const float*)d_in[9], (const float*)d_in[11]};
    float* out = (float*)d_out;

    float* h_ptr = nullptr;
    cudaGetSymbolAddress((void**)&h_ptr, g_h);

    cudaFuncSetAttribute(hgemm_kernel, cudaFuncAttributeMaxDynamicSharedMemorySize,
                         GEMM_SMEM);

    // Preprocessing (5 launches so the 6th launch — profiled by ncu -s 5 — is agg layer 0)
    zero_deg_kernel<<<(N_NODES + 255) / 256, 256>>>();
    degree_kernel<<<(N_EDGES + 255) / 256, 256>>>(src, dst);
    norm_kernel<<<(N_NODES + 255) / 256, 256>>>();
    scan_kernel<<<1, 1024>>>();
    fill_kernel<<<(N_EDGES + 255) / 256, 256>>>(src, dst);

    dim3 gemm_grid(D / BN, (N_NODES + BM - 1) / BM);   // (4, 157)

    // Layer 0: weighted agg on raw feat
    agg_kernel<1><<<N_NODES, 128>>>(feat);
    // Weight split (needed before first GEMM; independent of agg)
    wsplit_kernel<<<dim3(D / 32, D / 32, N_LAYERS), dim3(32, 8)>>>(W[0], W[1], W[2], W[3]);
    hgemm_kernel<<<gemm_grid, 256, GEMM_SMEM>>>(B[0], h_ptr, 0, 1);

    for (int l = 1; l < N_LAYERS; l++) {
        agg_kernel<0><<<N_NODES, 128>>>(h_ptr);
        hgemm_kernel<<<gemm_grid, 256, GEMM_SMEM>>>(B[l], h_ptr, l, l < 3 ? 1 : 0);
    }

    pool_kernel<<<dim3(N_GRAPHS, D / 128), 128>>>(out);
}

// round 6
// speedup vs baseline: 2.0012x; 2.0012x over previous
#include <cuda_runtime.h>
#include <cuda_fp16.h>
#include <cstdint>
#include <math.h>

#define N_NODES 20000
#define N_EDGES 160000
#define D 512
#define N_GRAPHS 16
#define NODES_PER_GRAPH 1250
#define N_LAYERS 4

// ---------------------------------------------------------------------------
// Device scratch (static globals — no allocations allowed)
// ---------------------------------------------------------------------------
__device__ float g_h[N_NODES * D];            // final-layer activations (fp32, for pool)
__device__ __half g_hb[N_NODES * D];          // intermediate activations (fp16, onorm-scaled)
__device__ __half g_a0[N_NODES * D];          // aggregated GEMM input (fp16)
__device__ __half g_wt[N_LAYERS * D * D];     // W^T fp16, [layer][n][k]
__device__ float g_onorm[N_NODES];
__device__ float g_inorm[N_NODES];
__device__ int g_outdeg[N_NODES];
__device__ int g_indeg[N_NODES];
__device__ int g_rowoff[N_NODES + 1];
__device__ int g_cursor[N_NODES];
__device__ int g_csr[N_EDGES];                // src ids grouped by dst

__device__ __forceinline__ uint32_t smem_u32(const void* p) {
    uint32_t a;
    asm("{ .reg .u64 t; cvta.to.shared.u64 t, %1; cvt.u32.u64 %0, t; }" : "=r"(a) : "l"(p));
    return a;
}

__device__ __forceinline__ void cp_async_16(uint32_t dst, const void* src, int src_size) {
    asm volatile("cp.async.cg.shared.global [%0], [%1], 16, %2;"
                 :: "r"(dst), "l"(src), "r"(src_size) : "memory");
}

__device__ __forceinline__ void ldsm_x4(uint32_t* r, uint32_t addr) {
    asm volatile("ldmatrix.sync.aligned.m8n8.x4.shared.b16 {%0,%1,%2,%3}, [%4];"
                 : "=r"(r[0]), "=r"(r[1]), "=r"(r[2]), "=r"(r[3]) : "r"(addr));
}

__device__ __forceinline__ void mma_16816(float* d, const uint32_t* a,
                                          uint32_t b0, uint32_t b1) {
    asm volatile(
        "mma.sync.aligned.m16n8k16.row.col.f32.f16.f16.f32 "
        "{%0,%1,%2,%3}, {%4,%5,%6,%7}, {%8,%9}, {%0,%1,%2,%3};"
        : "+f"(d[0]), "+f"(d[1]), "+f"(d[2]), "+f"(d[3])
        : "r"(a[0]), "r"(a[1]), "r"(a[2]), "r"(a[3]), "r"(b0), "r"(b1));
}

// ---------------------------------------------------------------------------
// Graph preprocessing
// ---------------------------------------------------------------------------
__global__ void degree_kernel(const int* __restrict__ src, const int* __restrict__ dst) {
    int e = blockIdx.x * blockDim.x + threadIdx.x;
    if (e < N_EDGES) {
        atomicAdd(&g_outdeg[src[e]], 1);
        atomicAdd(&g_indeg[dst[e]], 1);
    }
}

// Fused: norms + single-block exclusive scan of g_indeg -> g_rowoff / g_cursor.
// No big local prefix array (avoids spills): second pass re-reads g_indeg (L2-hot).
__global__ void scan_norm_kernel() {
    const int CH = (N_NODES + 1023) / 1024;  // 20
    __shared__ int wsum[32];
    int tid = threadIdx.x;
    int base = tid * CH;

    int s = 0;
#pragma unroll 4
    for (int i = 0; i < CH; i++) {
        int idx = base + i;
        if (idx < N_NODES) {
            int id = g_indeg[idx];
            int od = g_outdeg[idx];
            g_inorm[idx] = id > 0 ? rsqrtf((float)id) : 0.0f;
            g_onorm[idx] = od > 0 ? rsqrtf((float)od) : 0.0f;
            s += id;
        }
    }

    int lane = tid & 31, w = tid >> 5;
    int incl = s;
#pragma unroll
    for (int off = 1; off < 32; off <<= 1) {
        int n = __shfl_up_sync(0xffffffffu, incl, off);
        if (lane >= off) incl += n;
    }
    if (lane == 31) wsum[w] = incl;
    __syncthreads();
    if (w == 0) {
        int x = wsum[lane];
#pragma unroll
        for (int off = 1; off < 32; off <<= 1) {
            int n = __shfl_up_sync(0xffffffffu, x, off);
            if (lane >= off) x += n;
        }
        wsum[lane] = x;
    }
    __syncthreads();

    int run = incl - s + (w > 0 ? wsum[w - 1] : 0);
#pragma unroll 4
    for (int i = 0; i < CH; i++) {
        int idx = base + i;
        if (idx < N_NODES) {
            g_rowoff[idx] = run;
            g_cursor[idx] = run;
            run += g_indeg[idx];
        }
    }
    if (tid == 1023) g_rowoff[N_NODES] = wsum[31];
}

__global__ void fill_kernel(const int* __restrict__ src, const int* __restrict__ dst) {
    int e = blockIdx.x * blockDim.x + threadIdx.x;
    if (e < N_EDGES) {
        int d = dst[e];
        int pos = atomicAdd(&g_cursor[d], 1);
        g_csr[pos] = src[e];
    }
}

// ---------------------------------------------------------------------------
// W transpose + fp16: WT[layer][n][k] = fp16(W[k][n])
// ---------------------------------------------------------------------------
__global__ void wsplit_kernel(const float* __restrict__ W0, const float* __restrict__ W1,
                              const float* __restrict__ W2, const float* __restrict__ W3) {
    __shared__ float tile[32][33];
    int layer = blockIdx.z;
    const float* W = layer == 0 ? W0 : layer == 1 ? W1 : layer == 2 ? W2 : W3;
    int k0 = blockIdx.x * 32, n0 = blockIdx.y * 32;
    for (int i = threadIdx.y; i < 32; i += 8)
        tile[i][threadIdx.x] = W[(size_t)(k0 + i) * D + n0 + threadIdx.x];
    __syncthreads();
    for (int i = threadIdx.y; i < 32; i += 8) {
        float x = tile[threadIdx.x][i];                       // W[k0+tx][n0+i]
        size_t idx = (size_t)layer * D * D + (size_t)(n0 + i) * D + (k0 + threadIdx.x);
        g_wt[idx] = __float2half(x);
    }
}

// ---------------------------------------------------------------------------
// Layer-0 aggregation: fp32 feat, per-edge out_norm weight, fused in_norm, fp16 out.
// ---------------------------------------------------------------------------
__global__ __launch_bounds__(128)
void agg_feat_kernel(const float* __restrict__ h) {
    int node = blockIdx.x;
    int lane4 = threadIdx.x * 4;
    int beg = g_rowoff[node], end = g_rowoff[node + 1];
    float ax = 0.f, ay = 0.f, az = 0.f, aw = 0.f;

    int e = beg;
    for (; e + 4 <= end; e += 4) {
        int s0 = g_csr[e], s1 = g_csr[e + 1], s2 = g_csr[e + 2], s3 = g_csr[e + 3];
        float4 v0 = *reinterpret_cast<const float4*>(&h[(size_t)s0 * D + lane4]);
        float4 v1 = *reinterpret_cast<const float4*>(&h[(size_t)s1 * D + lane4]);
        float4 v2 = *reinterpret_cast<const float4*>(&h[(size_t)s2 * D + lane4]);
        float4 v3 = *reinterpret_cast<const float4*>(&h[(size_t)s3 * D + lane4]);
        float w0 = g_onorm[s0], w1 = g_onorm[s1], w2 = g_onorm[s2], w3 = g_onorm[s3];
        ax = fmaf(v0.x, w0, ax); ay = fmaf(v0.y, w0, ay); az = fmaf(v0.z, w0, az); aw = fmaf(v0.w, w0, aw);
        ax = fmaf(v1.x, w1, ax); ay = fmaf(v1.y, w1, ay); az = fmaf(v1.z, w1, az); aw = fmaf(v1.w, w1, aw);
        ax = fmaf(v2.x, w2, ax); ay = fmaf(v2.y, w2, ay); az = fmaf(v2.z, w2, az); aw = fmaf(v2.w, w2, aw);
        ax = fmaf(v3.x, w3, ax); ay = fmaf(v3.y, w3, ay); az = fmaf(v3.z, w3, az); aw = fmaf(v3.w, w3, aw);
    }
    for (; e < end; ++e) {
        int s = g_csr[e];
        float w = g_onorm[s];
        float4 v = *reinterpret_cast<const float4*>(&h[(size_t)s * D + lane4]);
        ax = fmaf(v.x, w, ax); ay = fmaf(v.y, w, ay);
        az = fmaf(v.z, w, az); aw = fmaf(v.w, w, aw);
    }

    float sc = g_inorm[node];
    __half2 o01 = __floats2half2_rn(ax * sc, ay * sc);
    __half2 o23 = __floats2half2_rn(az * sc, aw * sc);
    uint2 word;
    word.x = *reinterpret_cast<uint32_t*>(&o01);
    word.y = *reinterpret_cast<uint32_t*>(&o23);
    *reinterpret_cast<uint2*>(&g_a0[(size_t)node * D + lane4]) = word;
}

// ---------------------------------------------------------------------------
// Layers 1-3 aggregation: fp16 input rows already out_norm-scaled; pure sum.
// ---------------------------------------------------------------------------
__global__ __launch_bounds__(128)
void agg_f16_kernel() {
    int node = blockIdx.x;
    int lane4 = threadIdx.x * 4;
    int beg = g_rowoff[node], end = g_rowoff[node + 1];
    float ax = 0.f, ay = 0.f, az = 0.f, aw = 0.f;

    int e = beg;
    for (; e + 4 <= end; e += 4) {
        int s0 = g_csr[e], s1 = g_csr[e + 1], s2 = g_csr[e + 2], s3 = g_csr[e + 3];
        uint2 u0 = *reinterpret_cast<const uint2*>(&g_hb[(size_t)s0 * D + lane4]);
        uint2 u1 = *reinterpret_cast<const uint2*>(&g_hb[(size_t)s1 * D + lane4]);
        uint2 u2 = *reinterpret_cast<const uint2*>(&g_hb[(size_t)s2 * D + lane4]);
        uint2 u3 = *reinterpret_cast<const uint2*>(&g_hb[(size_t)s3 * D + lane4]);
#pragma unroll
        for (int q = 0; q < 4; q++) {
            uint2 u = q == 0 ? u0 : q == 1 ? u1 : q == 2 ? u2 : u3;
            float2 f01 = __half22float2(*reinterpret_cast<__half2*>(&u.x));
            float2 f23 = __half22float2(*reinterpret_cast<__half2*>(&u.y));
            ax += f01.x; ay += f01.y; az += f23.x; aw += f23.y;
        }
    }
    for (; e < end; ++e) {
        int s = g_csr[e];
        uint2 u = *reinterpret_cast<const uint2*>(&g_hb[(size_t)s * D + lane4]);
        float2 f01 = __half22float2(*reinterpret_cast<__half2*>(&u.x));
        float2 f23 = __half22float2(*reinterpret_cast<__half2*>(&u.y));
        ax += f01.x; ay += f01.y; az += f23.x; aw += f23.y;
    }

    float sc = g_inorm[node];
    __half2 o01 = __floats2half2_rn(ax * sc, ay * sc);
    __half2 o23 = __floats2half2_rn(az * sc, aw * sc);
    uint2 word;
    word.x = *reinterpret_cast<uint32_t*>(&o01);
    word.y = *reinterpret_cast<uint32_t*>(&o23);
    *reinterpret_cast<uint2*>(&g_a0[(size_t)node * D + lane4]) = word;
}

// ---------------------------------------------------------------------------
// Pure-fp16 HMMA GEMM: acc = A @ WT^T, CTA 128x128, BK=64, 2-stage cp.async.
// mode==1: g_hb[row] = fp16(out_norm[row] * relu(acc+bias))   (layers 0-2)
// mode==0: g_h[row]  = acc + bias                             (layer 3)
// 2 CTAs/SM (73.7 KB smem each).
// ---------------------------------------------------------------------------
#define BM 128
#define BN 128
#define BK 64
#define NCHUNK (D / BK)                   // 8
#define PAD_K 72                          // row pitch elements (144 B, odd multiple of 16B)
#define TILE_BYTES (128 * PAD_K * 2)      // 18432
#define STAGE_BYTES (2 * TILE_BYTES)      // 36864 (A, B)
#define GEMM_SMEM (2 * STAGE_BYTES)       // 73728

__device__ __forceinline__ void gemm_load_stage(
    uint32_t sb, int c, int m0, int n0, int tid, const __half* wt)
{
    int k0 = c * BK;
    uint32_t stb = sb + (uint32_t)(c & 1) * STAGE_BYTES;
#pragma unroll
    for (int i = 0; i < 8; i++) {
        int id = tid + i * 256;          // 0..2047
        int t = id >> 10;                // 0=A, 1=B
        int r = (id >> 3) & 127;         // row within tile
        int kc = id & 7;                 // 16B chunk within BK
        uint32_t dst = stb + (uint32_t)t * TILE_BYTES + (uint32_t)r * (PAD_K * 2) + kc * 16;
        const __half* g;
        int size = 16;
        if (t == 0) {
            int row = m0 + r;
            if (row >= N_NODES) { row = 0; size = 0; }
            g = g_a0 + (size_t)row * D + k0 + kc * 8;
        } else {
            g = wt + (size_t)(n0 + r) * D + k0 + kc * 8;
        }
        cp_async_16(dst, g, size);
    }
    asm volatile("cp.async.commit_group;" ::: "memory");
}

__global__ __launch_bounds__(256, 2)
void hgemm_kernel(const float* __restrict__ bias, int layer, int mode)
{
    extern __shared__ char smem[];
    uint32_t sb = smem_u32(smem);
    int tid = threadIdx.x;
    int lane = tid & 31, wid = tid >> 5;
    int m0 = blockIdx.y * BM;
    int n0 = blockIdx.x * BN;
    int wm = (wid & 3) * 32;
    int wn = (wid >> 2) * 64;

    const __half* wt = g_wt + (size_t)layer * D * D;

    float acc[2][8][4];
#pragma unroll
    for (int i = 0; i < 2; i++)
#pragma unroll
        for (int j = 0; j < 8; j++)
#pragma unroll
            for (int k = 0; k < 4; k++) acc[i][j][k] = 0.0f;

    int lrow = lane & 15;
    uint32_t lcolb = (uint32_t)(lane >> 4) * 16;

    gemm_load_stage(sb, 0, m0, n0, tid, wt);

#pragma unroll 1
    for (int c = 0; c < NCHUNK; ++c) {
        if (c + 1 < NCHUNK) {
            gemm_load_stage(sb, c + 1, m0, n0, tid, wt);
            asm volatile("cp.async.wait_group 1;" ::: "memory");
        } else {
            asm volatile("cp.async.wait_group 0;" ::: "memory");
        }
        __syncthreads();

        uint32_t stb = sb + (uint32_t)(c & 1) * STAGE_BYTES;
        uint32_t at = stb;
        uint32_t bt = stb + TILE_BYTES;

#pragma unroll
        for (int kk = 0; kk < BK; kk += 16) {
            uint32_t kb = (uint32_t)kk * 2 + lcolb;
            uint32_t af[2][4], bf[4][4];
#pragma unroll
            for (int mi = 0; mi < 2; mi++)
                ldsm_x4(af[mi], at + (uint32_t)(wm + mi * 16 + lrow) * (PAD_K * 2) + kb);
#pragma unroll
            for (int nb = 0; nb < 4; nb++)
                ldsm_x4(bf[nb], bt + (uint32_t)(wn + nb * 16 + lrow) * (PAD_K * 2) + kb);
#pragma unroll
            for (int mi = 0; mi < 2; mi++)
#pragma unroll
                for (int nb = 0; nb < 4; nb++) {
                    mma_16816(acc[mi][nb * 2 + 0], af[mi], bf[nb][0], bf[nb][2]);
                    mma_16816(acc[mi][nb * 2 + 1], af[mi], bf[nb][1], bf[nb][3]);
                }
        }
        __syncthreads();
    }

    // Epilogue
    int rbase = m0 + wm + (lane >> 2);
    int cbase = n0 + wn + (lane & 3) * 2;
#pragma unroll
    for (int mi = 0; mi < 2; mi++) {
        int r0 = rbase + mi * 16;
        int r1 = r0 + 8;
        bool v0 = r0 < N_NODES, v1 = r1 < N_NODES;
        if (mode) {
            float s0 = v0 ? g_onorm[r0] : 0.0f;
            float s1 = v1 ? g_onorm[r1] : 0.0f;
#pragma unroll
            for (int ni = 0; ni < 8; ni++) {
                int col = cbase + ni * 8;
                float2 bv = *reinterpret_cast<const float2*>(&bias[col]);
                __half2 o0 = __floats2half2_rn(
                    fmaxf(acc[mi][ni][0] + bv.x, 0.f) * s0,
                    fmaxf(acc[mi][ni][1] + bv.y, 0.f) * s0);
                __half2 o1 = __floats2half2_rn(
                    fmaxf(acc[mi][ni][2] + bv.x, 0.f) * s1,
                    fmaxf(acc[mi][ni][3] + bv.y, 0.f) * s1);
                if (v0) *reinterpret_cast<uint32_t*>(&g_hb[(size_t)r0 * D + col]) =
                            *reinterpret_cast<uint32_t*>(&o0);
                if (v1) *reinterpret_cast<uint32_t*>(&g_hb[(size_t)r1 * D + col]) =
                            *reinterpret_cast<uint32_t*>(&o1);
            }
        } else {
#pragma unroll
            for (int ni = 0; ni < 8; ni++) {
                int col = cbase + ni * 8;
                float2 bv = *reinterpret_cast<const float2*>(&bias[col]);
                float2 o0, o1;
                o0.x = acc[mi][ni][0] + bv.x; o0.y = acc[mi][ni][1] + bv.y;
                o1.x = acc[mi][ni][2] + bv.x; o1.y = acc[mi][ni][3] + bv.y;
                if (v0) *reinterpret_cast<float2*>(&g_h[(size_t)r0 * D + col]) = o0;
                if (v1) *reinterpret_cast<float2*>(&g_h[(size_t)r1 * D + col]) = o1;
            }
        }
    }
}

// ---------------------------------------------------------------------------
// Mean pool per graph (graphs are contiguous blocks of 1250 nodes)
// ---------------------------------------------------------------------------
__global__ void pool_kernel(float* __restrict__ out) {
    int g = blockIdx.x;
    int c = blockIdx.y * 128 + threadIdx.x;
    const float* base = g_h + (size_t)g * NODES_PER_GRAPH * D;
    float s0 = 0.f, s1 = 0.f;
#pragma unroll 4
    for (int i = 0; i < NODES_PER_GRAPH; i += 2) {
        s0 += base[(size_t)i * D + c];
        s1 += base[(size_t)(i + 1) * D + c];
    }
    out[g * D + c] = (s0 + s1) * (1.0f / (float)NODES_PER_GRAPH);
}

// ---------------------------------------------------------------------------
// Launch
// ---------------------------------------------------------------------------
extern "C" void kernel_launch(void* const* d_in, const int* in_sizes, int n_in,
                              void* d_out, int out_size) {
    const float* feat = (const float*)d_in[0];
    const int* src = (const int*)d_in[1];
    const int* dst = (const int*)d_in[2];
    const float* W[4] = {(const float*)d_in[4], (const float*)d_in[6],
                         (const float*)d_in[8], (const float*)d_in[10]};
    const float* B[4] = {(const float*)d_in[5], (const float*)d_in[7],
                         (const float*)d_in[9], (const float*)d_in[11]};
    float* out = (float*)d_out;

    void *outdeg_ptr = nullptr, *indeg_ptr = nullptr;
    cudaGetSymbolAddress(&outdeg_ptr, g_outdeg);
    cudaGetSymbolAddress(&indeg_ptr, g_indeg);

    cudaFuncSetAttribute(hgemm_kernel, cudaFuncAttributeMaxDynamicSharedMemorySize,
                         GEMM_SMEM);

    // Preprocessing
    cudaMemsetAsync(outdeg_ptr, 0, N_NODES * sizeof(int));
    cudaMemsetAsync(indeg_ptr, 0, N_NODES * sizeof(int));
    degree_kernel<<<(N_EDGES + 255) / 256, 256>>>(src, dst);
    scan_norm_kernel<<<1, 1024>>>();
    fill_kernel<<<(N_EDGES + 255) / 256, 256>>>(src, dst);

    dim3 gemm_grid(D / BN, (N_NODES + BM - 1) / BM);   // (4, 157)

    // Layer 0
    agg_feat_kernel<<<N_NODES, 128>>>(feat);
    wsplit_kernel<<<dim3(D / 32, D / 32, N_LAYERS), dim3(32, 8)>>>(W[0], W[1], W[2], W[3]);
    hgemm_kernel<<<gemm_grid, 256, GEMM_SMEM>>>(B[0], 0, 1);

    // Layers 1-3
    for (int l = 1; l < N_LAYERS; l++) {
        agg_f16_kernel<<<N_NODES, 128>>>();
        hgemm_kernel<<<gemm_grid, 256, GEMM_SMEM>>>(B[l], l, l < 3 ? 1 : 0);
    }

    pool_kernel<<<dim3(N_GRAPHS, D / 128), 128>>>(out);
}